// round 1
// baseline (speedup 1.0000x reference)
#include <cuda_runtime.h>
#include <stdint.h>

// Problem constants
#define NBINS      32
#define NCH        64            // B*C = 8*8
#define HW         65536         // 256*256 pixels per channel
#define NSUB       2048          // fine histogram sub-bins over [0,1)
#define CTAS_PER_CH 8
#define NCTA1      (NCH * CTAS_PER_CH)      // 512
#define F4_PER_CTA ((HW / 4) / CTAS_PER_CH) // 2048 float4 per CTA
#define PAD        320           // +-5 sigma window = +-320 sub-bins
#define WIN        (2 * PAD)     // 640
#define CHUNK      (WIN / 8)     // 80 terms per thread (8 threads per bin)

#define AMPL   0.3989472f        // ER/RATIO = 1/2.5066
#define INV31  (1.0f / 31.0f)    // bin spacing (linspace(0,1,32))
#define K512   512.0f            // 1/(2*sigma^2), sigma = 1/32
#define DELTA  (1.0f / 2048.0f)  // sub-bin width

// Per-CTA partial histograms (counts). 512 * 2048 * 4B = 4 MB scratch.
__device__ unsigned int g_part[NCTA1 * NSUB];

// ---------------------------------------------------------------------------
// Kernel 1: fine count histogram per CTA slice (shared-memory atomics),
// then flush to a private global slab (no global atomics, no memset needed:
// every slab word is overwritten each launch -> deterministic & replay-safe).
// ---------------------------------------------------------------------------
__global__ __launch_bounds__(256, 8)
void hist_kernel(const float* __restrict__ x)
{
    __shared__ unsigned int h[NSUB];
    const int tid = threadIdx.x;

    #pragma unroll
    for (int i = tid; i < NSUB; i += 256) h[i] = 0u;
    __syncthreads();

    const float4* __restrict__ p =
        reinterpret_cast<const float4*>(x) + (size_t)blockIdx.x * F4_PER_CTA;

    #pragma unroll
    for (int i = tid; i < F4_PER_CTA; i += 256) {
        float4 v = p[i];
        int b0 = (int)(v.x * (float)NSUB);
        int b1 = (int)(v.y * (float)NSUB);
        int b2 = (int)(v.z * (float)NSUB);
        int b3 = (int)(v.w * (float)NSUB);
        b0 = min(NSUB - 1, max(0, b0));
        b1 = min(NSUB - 1, max(0, b1));
        b2 = min(NSUB - 1, max(0, b2));
        b3 = min(NSUB - 1, max(0, b3));
        atomicAdd(&h[b0], 1u);
        atomicAdd(&h[b1], 1u);
        atomicAdd(&h[b2], 1u);
        atomicAdd(&h[b3], 1u);
    }
    __syncthreads();

    unsigned int* __restrict__ slab = g_part + (size_t)blockIdx.x * NSUB;
    #pragma unroll
    for (int i = tid; i < NSUB; i += 256) slab[i] = h[i];
}

// ---------------------------------------------------------------------------
// Kernel 2: one CTA per channel. Merge the CTAS_PER_CH partial histograms
// into shared (zero-padded by +-PAD), then for each of the 32 output bins
// sum the Gaussian-weighted window. Weights via the lattice recurrence:
//   w(m+1) = w(m) * r(m),  r(m+1) = r(m) * g,  g = exp(-2*K512*DELTA^2)
// -> only 2 expf per 80-term chunk.
// ---------------------------------------------------------------------------
__global__ __launch_bounds__(256, 4)
void conv_kernel(float* __restrict__ out)
{
    __shared__ float h[NSUB + 2 * PAD];   // 2688 floats
    const int tid = threadIdx.x;
    const int ch  = blockIdx.x;           // 0..63

    const unsigned int* __restrict__ base = g_part + (size_t)ch * CTAS_PER_CH * NSUB;
    for (int i = tid; i < NSUB + 2 * PAD; i += 256) {
        int m = i - PAD;
        float s = 0.0f;
        if (m >= 0 && m < NSUB) {
            unsigned int c = 0;
            #pragma unroll
            for (int k = 0; k < CTAS_PER_CH; k++) c += base[k * NSUB + m];
            s = (float)c;
        }
        h[i] = s;
    }
    __syncthreads();

    const int j   = tid >> 3;   // output bin 0..31
    const int sub = tid & 7;    // 8 threads per bin

    const float cj = (float)j * INV31;
    // window start: round c_j to sub-bin grid, extend +-PAD
    const int m0 = (int)(cj * (float)NSUB) - PAD + sub * CHUNK;

    // first sub-bin center of this chunk
    const float x0 = ((float)m0 + 0.5f) * DELTA;
    const float d0 = x0 - cj;

    float w = __expf(-d0 * d0 * K512);
    float r = __expf(-K512 * DELTA * (2.0f * d0 + DELTA));
    const float g = __expf(-2.0f * K512 * DELTA * DELTA);

    float acc = 0.0f;
    #pragma unroll
    for (int k = 0; k < CHUNK; k++) {
        acc = fmaf(h[m0 + k + PAD], w, acc);
        w *= r;
        r *= g;
    }

    // reduce the 8-thread group (contiguous lanes)
    #pragma unroll
    for (int off = 4; off > 0; off >>= 1)
        acc += __shfl_down_sync(0xFFFFFFFFu, acc, off, 8);

    if (sub == 0)
        out[ch * NBINS + j] = acc * AMPL;
}

// ---------------------------------------------------------------------------
extern "C" void kernel_launch(void* const* d_in, const int* in_sizes, int n_in,
                              void* d_out, int out_size)
{
    const float* x = (const float*)d_in[0];   // [8,8,256,256] fp32
    float* out = (float*)d_out;               // [8,256,1,1] = 2048 fp32

    hist_kernel<<<NCTA1, 256>>>(x);
    conv_kernel<<<NCH, 256>>>(out);
}